// round 3
// baseline (speedup 1.0000x reference)
#include <cuda_runtime.h>
#include <cuda_bf16.h>

#define H 512
#define W 512
#define OW 510                 // windows per dim
#define PLANE (H * W)
#define WIN_PER_WARP 30        // 32 lanes -> 30 windows (need lane+2 in-warp)
#define COLGROUPS 17           // ceil(510 / 30)
#define NTASKS (OW * COLGROUPS)        // 510 * 17 = 8670 warp-tasks
#define WARPS_PER_BLOCK 4
#define NBLOCKS ((NTASKS + WARPS_PER_BLOCK - 1) / WARPS_PER_BLOCK)   // 2168

__device__ float g_part[NBLOCKS];

__global__ __launch_bounds__(WARPS_PER_BLOCK * 32)
void ml_main_kernel(const float* __restrict__ T, const float* __restrict__ V)
{
    const int warp_id  = threadIdx.x >> 5;
    const int lane     = threadIdx.x & 31;
    const int warp_gid = blockIdx.x * WARPS_PER_BLOCK + warp_id;

    float contrib = 0.0f;

    if (warp_gid < NTASKS) {
        const int r = warp_gid / COLGROUPS;        // window row 0..509
        const int g = warp_gid % COLGROUPS;        // column group 0..16
        const int x = g * WIN_PER_WARP + lane;     // pixel column 0..511

        // ---- column-segment stats over pixels (r..r+2, x): 24 values ----
        float sT0 = 0.f, sT1 = 0.f, sT2 = 0.f;
        float s00 = 0.f, s01 = 0.f, s02 = 0.f, s11 = 0.f, s12 = 0.f, s22 = 0.f;
        float sV0 = 0.f, sV1 = 0.f, sV2 = 0.f;
        float q0 = 0.f, q1 = 0.f, q2 = 0.f;
        float m00 = 0.f, m01 = 0.f, m02 = 0.f;
        float m10 = 0.f, m11 = 0.f, m12 = 0.f;
        float m20 = 0.f, m21 = 0.f, m22 = 0.f;

        #pragma unroll
        for (int dr = 0; dr < 3; dr++) {
            const int base = (r + dr) * W + x;
            const float t0 = __ldg(T + 0 * PLANE + base);
            const float t1 = __ldg(T + 1 * PLANE + base);
            const float t2 = __ldg(T + 2 * PLANE + base);
            const float v0 = __ldg(V + 0 * PLANE + base);
            const float v1 = __ldg(V + 1 * PLANE + base);
            const float v2 = __ldg(V + 2 * PLANE + base);

            sT0 += t0; sT1 += t1; sT2 += t2;
            s00 += t0 * t0; s01 += t0 * t1; s02 += t0 * t2;
            s11 += t1 * t1; s12 += t1 * t2; s22 += t2 * t2;

            sV0 += v0; sV1 += v1; sV2 += v2;
            q0 += v0 * v0; q1 += v1 * v1; q2 += v2 * v2;

            m00 += t0 * v0; m01 += t0 * v1; m02 += t0 * v2;
            m10 += t1 * v0; m11 += t1 * v1; m12 += t1 * v2;
            m20 += t2 * v0; m21 += t2 * v1; m22 += t2 * v2;
        }

        // ---- window stats: colseg(x) + colseg(x+1) + colseg(x+2) via shuffles ----
        #define WSUM(s) (s + __shfl_down_sync(0xffffffffu, s, 1) \
                           + __shfl_down_sync(0xffffffffu, s, 2))
        const float wT0 = WSUM(sT0), wT1 = WSUM(sT1), wT2 = WSUM(sT2);
        const float w00 = WSUM(s00), w01 = WSUM(s01), w02 = WSUM(s02);
        const float w11 = WSUM(s11), w12 = WSUM(s12), w22 = WSUM(s22);
        const float wV0 = WSUM(sV0), wV1 = WSUM(sV1), wV2 = WSUM(sV2);
        const float wq0 = WSUM(q0),  wq1 = WSUM(q1),  wq2 = WSUM(q2);
        const float n00 = WSUM(m00), n01 = WSUM(m01), n02 = WSUM(m02);
        const float n10 = WSUM(m10), n11 = WSUM(m11), n12 = WSUM(m12);
        const float n20 = WSUM(m20), n21 = WSUM(m21), n22 = WSUM(m22);
        #undef WSUM

        if (lane < WIN_PER_WARP) {      // window column = x (<= 509 guaranteed)
            const float inv9 = 1.0f / 9.0f;
            const float eps9 = 1e-7f * inv9;

            const float mu0 = wT0 * inv9, mu1 = wT1 * inv9, mu2 = wT2 * inv9;

            const float a00 = w00 * inv9 - mu0 * mu0 + eps9;
            const float a01 = w01 * inv9 - mu0 * mu1;
            const float a02 = w02 * inv9 - mu0 * mu2;
            const float a11 = w11 * inv9 - mu1 * mu1 + eps9;
            const float a12 = w12 * inv9 - mu1 * mu2;
            const float a22 = w22 * inv9 - mu2 * mu2 + eps9;

            const float c00 = a11 * a22 - a12 * a12;
            const float c01 = a02 * a12 - a01 * a22;
            const float c02 = a01 * a12 - a02 * a11;
            const float c11 = a00 * a22 - a02 * a02;
            const float c12 = a01 * a02 - a00 * a12;
            const float c22 = a00 * a11 - a01 * a01;
            const float det = a00 * c00 + a01 * c01 + a02 * c02;
            const float rdet = 1.0f / det;
            const float i00 = c00 * rdet, i01 = c01 * rdet, i02 = c02 * rdet;
            const float i11 = c11 * rdet, i12 = c12 * rdet, i22 = c22 * rdet;

            // channel 0
            {
                const float u0 = n00 - mu0 * wV0;
                const float u1 = n10 - mu1 * wV0;
                const float u2 = n20 - mu2 * wV0;
                const float quad = i00 * u0 * u0 + i11 * u1 * u1 + i22 * u2 * u2
                                 + 2.f * (i01 * u0 * u1 + i02 * u0 * u2 + i12 * u1 * u2);
                contrib += wq0 - inv9 * (wV0 * wV0 + quad);
            }
            // channel 1
            {
                const float u0 = n01 - mu0 * wV1;
                const float u1 = n11 - mu1 * wV1;
                const float u2 = n21 - mu2 * wV1;
                const float quad = i00 * u0 * u0 + i11 * u1 * u1 + i22 * u2 * u2
                                 + 2.f * (i01 * u0 * u1 + i02 * u0 * u2 + i12 * u1 * u2);
                contrib += wq1 - inv9 * (wV1 * wV1 + quad);
            }
            // channel 2
            {
                const float u0 = n02 - mu0 * wV2;
                const float u1 = n12 - mu1 * wV2;
                const float u2 = n22 - mu2 * wV2;
                const float quad = i00 * u0 * u0 + i11 * u1 * u1 + i22 * u2 * u2
                                 + 2.f * (i01 * u0 * u1 + i02 * u0 * u2 + i12 * u1 * u2);
                contrib += wq2 - inv9 * (wV2 * wV2 + quad);
            }
        }
    }

    // warp reduction
    #pragma unroll
    for (int off = 16; off > 0; off >>= 1)
        contrib += __shfl_xor_sync(0xffffffffu, contrib, off);

    __shared__ float wsum[WARPS_PER_BLOCK];
    if ((threadIdx.x & 31) == 0) wsum[warp_id] = contrib;
    __syncthreads();
    if (threadIdx.x == 0) {
        float s = 0.f;
        #pragma unroll
        for (int i = 0; i < WARPS_PER_BLOCK; i++) s += wsum[i];
        g_part[blockIdx.x] = s;
    }
}

__global__ __launch_bounds__(256)
void ml_reduce_kernel(float* __restrict__ out)
{
    __shared__ double dred[256];
    double s = 0.0;
    for (int i = threadIdx.x; i < NBLOCKS; i += 256)
        s += (double)g_part[i];
    dred[threadIdx.x] = s;
    __syncthreads();
    #pragma unroll
    for (int st = 128; st > 0; st >>= 1) {
        if (threadIdx.x < st) dred[threadIdx.x] += dred[threadIdx.x + st];
        __syncthreads();
    }
    if (threadIdx.x == 0) out[0] = (float)dred[0];
}

extern "C" void kernel_launch(void* const* d_in, const int* in_sizes, int n_in,
                              void* d_out, int out_size)
{
    const float* target = (const float*)d_in[0];
    const float* style  = (const float*)d_in[1];
    float* out = (float*)d_out;

    ml_main_kernel<<<NBLOCKS, WARPS_PER_BLOCK * 32>>>(target, style);
    ml_reduce_kernel<<<1, 256>>>(out);
}

// round 4
// speedup vs baseline: 1.3810x; 1.3810x over previous
#include <cuda_runtime.h>
#include <cuda_bf16.h>

#define H 512
#define W 512
#define OW 510                 // windows per dim
#define PLANE (H * W)
#define WIN_PER_WARP 30        // 32 lanes -> 30 windows (need lane+2 in-warp)
#define COLGROUPS 17           // ceil(510 / 30)
#define NTASKS (OW * COLGROUPS)        // 510 * 17 = 8670 warp-tasks
#define WARPS_PER_BLOCK 4
#define NBLOCKS ((NTASKS + WARPS_PER_BLOCK - 1) / WARPS_PER_BLOCK)   // 2168

__device__ double       g_accum;   // zero-init; restored to 0 each call
__device__ unsigned int g_cnt;     // zero-init; restored to 0 each call

__global__ __launch_bounds__(WARPS_PER_BLOCK * 32)
void ml_fused_kernel(const float* __restrict__ T, const float* __restrict__ V,
                     float* __restrict__ out)
{
    const int warp_id  = threadIdx.x >> 5;
    const int lane     = threadIdx.x & 31;
    const int warp_gid = blockIdx.x * WARPS_PER_BLOCK + warp_id;

    float contrib = 0.0f;

    if (warp_gid < NTASKS) {
        const int r = warp_gid / COLGROUPS;        // window row 0..509
        const int g = warp_gid % COLGROUPS;        // column group 0..16
        const int x = g * WIN_PER_WARP + lane;     // pixel column 0..511

        // ---- column-segment stats over pixels (r..r+2, x): 24 values ----
        float sT0 = 0.f, sT1 = 0.f, sT2 = 0.f;
        float s00 = 0.f, s01 = 0.f, s02 = 0.f, s11 = 0.f, s12 = 0.f, s22 = 0.f;
        float sV0 = 0.f, sV1 = 0.f, sV2 = 0.f;
        float q0 = 0.f, q1 = 0.f, q2 = 0.f;
        float m00 = 0.f, m01 = 0.f, m02 = 0.f;
        float m10 = 0.f, m11 = 0.f, m12 = 0.f;
        float m20 = 0.f, m21 = 0.f, m22 = 0.f;

        #pragma unroll
        for (int dr = 0; dr < 3; dr++) {
            const int base = (r + dr) * W + x;
            const float t0 = __ldg(T + 0 * PLANE + base);
            const float t1 = __ldg(T + 1 * PLANE + base);
            const float t2 = __ldg(T + 2 * PLANE + base);
            const float v0 = __ldg(V + 0 * PLANE + base);
            const float v1 = __ldg(V + 1 * PLANE + base);
            const float v2 = __ldg(V + 2 * PLANE + base);

            sT0 += t0; sT1 += t1; sT2 += t2;
            s00 += t0 * t0; s01 += t0 * t1; s02 += t0 * t2;
            s11 += t1 * t1; s12 += t1 * t2; s22 += t2 * t2;

            sV0 += v0; sV1 += v1; sV2 += v2;
            q0 += v0 * v0; q1 += v1 * v1; q2 += v2 * v2;

            m00 += t0 * v0; m01 += t0 * v1; m02 += t0 * v2;
            m10 += t1 * v0; m11 += t1 * v1; m12 += t1 * v2;
            m20 += t2 * v0; m21 += t2 * v1; m22 += t2 * v2;
        }

        // ---- window stats: colseg(x) + colseg(x+1) + colseg(x+2) via shuffles ----
        #define WSUM(s) (s + __shfl_down_sync(0xffffffffu, s, 1) \
                           + __shfl_down_sync(0xffffffffu, s, 2))
        const float wT0 = WSUM(sT0), wT1 = WSUM(sT1), wT2 = WSUM(sT2);
        const float w00 = WSUM(s00), w01 = WSUM(s01), w02 = WSUM(s02);
        const float w11 = WSUM(s11), w12 = WSUM(s12), w22 = WSUM(s22);
        const float wV0 = WSUM(sV0), wV1 = WSUM(sV1), wV2 = WSUM(sV2);
        const float wq0 = WSUM(q0),  wq1 = WSUM(q1),  wq2 = WSUM(q2);
        const float n00 = WSUM(m00), n01 = WSUM(m01), n02 = WSUM(m02);
        const float n10 = WSUM(m10), n11 = WSUM(m11), n12 = WSUM(m12);
        const float n20 = WSUM(m20), n21 = WSUM(m21), n22 = WSUM(m22);
        #undef WSUM

        if (lane < WIN_PER_WARP) {      // window column = x (<= 509 guaranteed)
            const float inv9 = 1.0f / 9.0f;
            const float eps9 = 1e-7f * inv9;

            const float mu0 = wT0 * inv9, mu1 = wT1 * inv9, mu2 = wT2 * inv9;

            const float a00 = w00 * inv9 - mu0 * mu0 + eps9;
            const float a01 = w01 * inv9 - mu0 * mu1;
            const float a02 = w02 * inv9 - mu0 * mu2;
            const float a11 = w11 * inv9 - mu1 * mu1 + eps9;
            const float a12 = w12 * inv9 - mu1 * mu2;
            const float a22 = w22 * inv9 - mu2 * mu2 + eps9;

            const float c00 = a11 * a22 - a12 * a12;
            const float c01 = a02 * a12 - a01 * a22;
            const float c02 = a01 * a12 - a02 * a11;
            const float c11 = a00 * a22 - a02 * a02;
            const float c12 = a01 * a02 - a00 * a12;
            const float c22 = a00 * a11 - a01 * a01;
            const float det = a00 * c00 + a01 * c01 + a02 * c02;
            const float rdet = 1.0f / det;
            const float i00 = c00 * rdet, i01 = c01 * rdet, i02 = c02 * rdet;
            const float i11 = c11 * rdet, i12 = c12 * rdet, i22 = c22 * rdet;

            // channel 0
            {
                const float u0 = n00 - mu0 * wV0;
                const float u1 = n10 - mu1 * wV0;
                const float u2 = n20 - mu2 * wV0;
                const float quad = i00 * u0 * u0 + i11 * u1 * u1 + i22 * u2 * u2
                                 + 2.f * (i01 * u0 * u1 + i02 * u0 * u2 + i12 * u1 * u2);
                contrib += wq0 - inv9 * (wV0 * wV0 + quad);
            }
            // channel 1
            {
                const float u0 = n01 - mu0 * wV1;
                const float u1 = n11 - mu1 * wV1;
                const float u2 = n21 - mu2 * wV1;
                const float quad = i00 * u0 * u0 + i11 * u1 * u1 + i22 * u2 * u2
                                 + 2.f * (i01 * u0 * u1 + i02 * u0 * u2 + i12 * u1 * u2);
                contrib += wq1 - inv9 * (wV1 * wV1 + quad);
            }
            // channel 2
            {
                const float u0 = n02 - mu0 * wV2;
                const float u1 = n12 - mu1 * wV2;
                const float u2 = n22 - mu2 * wV2;
                const float quad = i00 * u0 * u0 + i11 * u1 * u1 + i22 * u2 * u2
                                 + 2.f * (i01 * u0 * u1 + i02 * u0 * u2 + i12 * u1 * u2);
                contrib += wq2 - inv9 * (wV2 * wV2 + quad);
            }
        }
    }

    // warp reduction
    #pragma unroll
    for (int off = 16; off > 0; off >>= 1)
        contrib += __shfl_xor_sync(0xffffffffu, contrib, off);

    __shared__ float wsum[WARPS_PER_BLOCK];
    __shared__ bool  is_last;
    if (lane == 0) wsum[warp_id] = contrib;
    __syncthreads();

    if (threadIdx.x == 0) {
        float s = 0.f;
        #pragma unroll
        for (int i = 0; i < WARPS_PER_BLOCK; i++) s += wsum[i];
        atomicAdd(&g_accum, (double)s);
        __threadfence();
        unsigned int prev = atomicAdd(&g_cnt, 1u);
        is_last = (prev == NBLOCKS - 1);
    }
    __syncthreads();

    if (is_last && threadIdx.x == 0) {
        __threadfence();                 // ensure all atomics to g_accum visible
        out[0] = (float)g_accum;
        g_accum = 0.0;                   // restore invariants for next replay
        g_cnt   = 0;
    }
}

extern "C" void kernel_launch(void* const* d_in, const int* in_sizes, int n_in,
                              void* d_out, int out_size)
{
    const float* target = (const float*)d_in[0];
    const float* style  = (const float*)d_in[1];
    float* out = (float*)d_out;

    ml_fused_kernel<<<NBLOCKS, WARPS_PER_BLOCK * 32>>>(target, style, out);
}